// round 1
// baseline (speedup 1.0000x reference)
#include <cuda_runtime.h>
#include <cuda_bf16.h>

// Focal cross-entropy sum over N rows, 2 classes.
// loss_i = -(oh0*l0*prb1^2 + oh1*l1*prb0^2), summed over i, where
//   d = p1-p0, lse = log(1+exp(d)), l0=-lse, l1=d-lse,
//   prb1=exp(l1)=sigmoid(d), prb0=exp(l0),
//   t = gold>=0.5 ; oh1 = t?0.25:0 ; oh0 = (1-oh1)*0.75.

#define GAMMA_ALPHA 0.25f

static constexpr int BLOCKS = 2048;
static constexpr int THREADS = 256;

__device__ float g_partials[BLOCKS];

__device__ __forceinline__ float row_loss(float p0, float p1, float gold) {
    float d = p1 - p0;
    // lse = log(1 + exp(d)) computed stably
    float e  = __expf(-fabsf(d));
    float lse = fmaxf(d, 0.0f) + __logf(1.0f + e);
    float l0 = -lse;         // log prb0
    float l1 = d - lse;      // log prb1
    float prb0 = __expf(l0);
    float prb1 = __expf(l1);
    bool t = (gold >= 0.5f);
    float oh1 = t ? 0.25f   : 0.0f;
    float oh0 = t ? 0.5625f : 0.75f;   // (1 - oh1) * 0.75
    // focal0 = (1-prb0)^2 = prb1^2 ; focal1 = prb0^2
    return -(oh0 * l0 * prb1 * prb1 + oh1 * l1 * prb0 * prb0);
}

__global__ void __launch_bounds__(THREADS)
focal_sum_kernel(const float* __restrict__ pred,
                 const float* __restrict__ gold,
                 int n_rows) {
    const float4* pred4 = reinterpret_cast<const float4*>(pred);
    const float4* gold4 = reinterpret_cast<const float4*>(gold);

    int tid    = blockIdx.x * THREADS + threadIdx.x;
    int stride = BLOCKS * THREADS;

    float acc = 0.0f;

    // 4 rows per iteration: gold4[i] covers rows 4i..4i+3,
    // pred4[2i] covers rows 4i,4i+1 ; pred4[2i+1] covers rows 4i+2,4i+3.
    int n_quads = n_rows >> 2;
    for (int i = tid; i < n_quads; i += stride) {
        float4 g  = gold4[i];
        float4 pa = pred4[2 * i];
        float4 pb = pred4[2 * i + 1];
        acc += row_loss(pa.x, pa.y, g.x);
        acc += row_loss(pa.z, pa.w, g.y);
        acc += row_loss(pb.x, pb.y, g.z);
        acc += row_loss(pb.z, pb.w, g.w);
    }
    // Tail rows (n_rows not multiple of 4)
    int tail_start = n_quads << 2;
    for (int r = tail_start + tid; r < n_rows; r += stride) {
        acc += row_loss(pred[2 * r], pred[2 * r + 1], gold[r]);
    }

    // Warp reduction
    #pragma unroll
    for (int off = 16; off > 0; off >>= 1)
        acc += __shfl_xor_sync(0xFFFFFFFFu, acc, off);

    __shared__ float warp_sums[THREADS / 32];
    int lane = threadIdx.x & 31;
    int wid  = threadIdx.x >> 5;
    if (lane == 0) warp_sums[wid] = acc;
    __syncthreads();

    if (wid == 0) {
        float v = (lane < THREADS / 32) ? warp_sums[lane] : 0.0f;
        #pragma unroll
        for (int off = 16; off > 0; off >>= 1)
            v += __shfl_xor_sync(0xFFFFFFFFu, v, off);
        if (lane == 0) g_partials[blockIdx.x] = v;
    }
}

__global__ void __launch_bounds__(1024)
final_reduce_kernel(float* __restrict__ out) {
    __shared__ float smem[1024];
    int tid = threadIdx.x;
    float v = 0.0f;
    #pragma unroll
    for (int i = tid; i < BLOCKS; i += 1024)
        v += g_partials[i];
    smem[tid] = v;
    __syncthreads();
    #pragma unroll
    for (int s = 512; s >= 32; s >>= 1) {
        if (tid < s) smem[tid] += smem[tid + s];
        __syncthreads();
    }
    if (tid < 32) {
        float w = smem[tid];
        #pragma unroll
        for (int off = 16; off > 0; off >>= 1)
            w += __shfl_xor_sync(0xFFFFFFFFu, w, off);
        if (tid == 0) out[0] = w;   // CORR = 1.0
    }
}

extern "C" void kernel_launch(void* const* d_in, const int* in_sizes, int n_in,
                              void* d_out, int out_size) {
    const float* pred = (const float*)d_in[0];   // [N, 2] f32
    const float* gold = (const float*)d_in[1];   // [N]    f32
    int n_rows = in_sizes[1];

    focal_sum_kernel<<<BLOCKS, THREADS>>>(pred, gold, n_rows);
    final_reduce_kernel<<<1, 1024>>>((float*)d_out);
}